// round 1
// baseline (speedup 1.0000x reference)
#include <cuda_runtime.h>
#include <math.h>
#include <float.h>

#define OUTD    12
#define N_VOX   1728              // 12*12*12
#define N_ROIS  128
#define N_PTS   160000
#define NCH     64
#define KMAX    64                // cap on points per (roi,voxel); fallback handles overflow
#define NRV     (N_ROIS * N_VOX)  // 221184

// Scratch: per-(roi,voxel) point lists. __device__ globals are the sanctioned scratch path.
__device__ int d_count[NRV];
__device__ int d_list[NRV * KMAX];

// ---------------------------------------------------------------------------
// Kernel 1: zero the counters (re-run every graph replay).
// ---------------------------------------------------------------------------
__global__ void zero_counts_kernel() {
    int i = blockIdx.x * blockDim.x + threadIdx.x;
    if (i < NRV) d_count[i] = 0;
}

// ---------------------------------------------------------------------------
// Kernel 2: one thread per point, loop over all 128 ROIs (derived params in smem).
// Quick-reject via bounding circle (conservative margin), then exact reference test.
// ---------------------------------------------------------------------------
__global__ __launch_bounds__(256) void build_lists_kernel(
    const float* __restrict__ rois, const float* __restrict__ pts)
{
    __shared__ float4 sA[N_ROIS];  // {cx, cy, r2_margin, cz}
    __shared__ float4 sB[N_ROIS];  // {cosa, sina, hdx, hdy}
    __shared__ float4 sC[N_ROIS];  // {hdz, vx, vy, vz}

    int t = threadIdx.x;
    if (t < N_ROIS) {
        const float* R = rois + t * 7;
        float cx = R[0], cy = R[1], cz = R[2];
        float dx = R[3], dy = R[4], dz = R[5];
        float ry = R[6];
        float hdx = dx * 0.5f, hdy = dy * 0.5f, hdz = dz * 0.5f;
        float r2  = (hdx * hdx + hdy * hdy) * 1.0002f + 1e-6f;  // conservative
        float ca  = cosf(-ry), sa = sinf(-ry);
        sA[t] = make_float4(cx, cy, r2, cz);
        sB[t] = make_float4(ca, sa, hdx, hdy);
        sC[t] = make_float4(hdz, dx / (float)OUTD, dy / (float)OUTD, dz / (float)OUTD);
    }
    __syncthreads();

    int p = blockIdx.x * blockDim.x + t;
    if (p >= N_PTS) return;
    float px = pts[3 * p + 0];
    float py = pts[3 * p + 1];
    float pz = pts[3 * p + 2];

    #pragma unroll 4
    for (int r = 0; r < N_ROIS; r++) {
        float4 A = sA[r];
        float sx = px - A.x;
        float sy = py - A.y;
        float d2 = sx * sx + sy * sy;
        if (d2 > A.z) continue;                 // ~99.8% rejected here

        float sz = pz - A.w;
        float4 B = sB[r];
        float4 C = sC[r];
        float lx = sx * B.x - sy * B.y;         // rotate into roi frame (angle = -ry)
        float ly = sx * B.y + sy * B.x;
        // exact replication of reference predicate
        bool in_box = (lx > -B.z) && (lx < B.z) &&
                      (ly > -B.w) && (ly < B.w) &&
                      (fabsf(sz - C.x) <= C.x);
        if (!in_box) continue;

        int xi = min(OUTD - 1, max(0, (int)floorf((lx + B.z) / C.y)));
        int yi = min(OUTD - 1, max(0, (int)floorf((ly + B.w) / C.z)));
        int zi = min(OUTD - 1, max(0, (int)floorf(sz / C.w)));
        int rv = r * N_VOX + xi * (OUTD * OUTD) + yi * OUTD + zi;
        int c = atomicAdd(&d_count[rv], 1);
        if (c < KMAX) d_list[rv * KMAX + c] = p;
    }
}

// ---------------------------------------------------------------------------
// Kernel 3: one warp per (roi,voxel). Lane handles 2 channels (float2).
// Empty voxel -> write zeros. Else max over listed points' feature rows
// (coalesced 256B row loads). Overflow (n > KMAX) -> full rescan fallback.
// ---------------------------------------------------------------------------
__global__ __launch_bounds__(256) void pool_kernel(
    const float* __restrict__ rois, const float* __restrict__ pts,
    const float* __restrict__ feat, float* __restrict__ out)
{
    int gtid = blockIdx.x * blockDim.x + threadIdx.x;
    int warp = gtid >> 5;
    int lane = threadIdx.x & 31;
    if (warp >= NRV) return;

    int n = d_count[warp];
    float2* o = (float2*)(out + (size_t)warp * NCH);
    if (n == 0) {
        o[lane] = make_float2(0.f, 0.f);
        return;
    }

    float mx0 = -FLT_MAX, mx1 = -FLT_MAX;
    int m = min(n, KMAX);
    const int* lst = &d_list[warp * KMAX];
    for (int j = 0; j < m; j++) {
        int pid = lst[j];                                     // warp-uniform load
        float2 v = ((const float2*)(feat + (size_t)pid * NCH))[lane];
        mx0 = fmaxf(mx0, v.x);
        mx1 = fmaxf(mx1, v.y);
    }

    if (n > KMAX) {
        // Correctness fallback (statistically never taken): rescan all points.
        int r = warp / N_VOX, vox = warp % N_VOX;
        int xi = vox / (OUTD * OUTD), yi = (vox / OUTD) % OUTD, zi = vox % OUTD;
        const float* R = rois + r * 7;
        float cx = R[0], cy = R[1], cz = R[2];
        float dx = R[3], dy = R[4], dz = R[5];
        float ry = R[6];
        float hdx = dx * 0.5f, hdy = dy * 0.5f, hdz = dz * 0.5f;
        float ca = cosf(-ry), sa = sinf(-ry);
        float vx = dx / (float)OUTD, vy = dy / (float)OUTD, vz = dz / (float)OUTD;
        for (int base = 0; base < N_PTS; base += 32) {
            int p = base + lane;
            bool hit = false;
            if (p < N_PTS) {
                float sx = pts[3 * p + 0] - cx;
                float sy = pts[3 * p + 1] - cy;
                float sz = pts[3 * p + 2] - cz;
                float lx = sx * ca - sy * sa;
                float ly = sx * sa + sy * ca;
                if ((lx > -hdx) && (lx < hdx) && (ly > -hdy) && (ly < hdy) &&
                    (fabsf(sz - hdz) <= hdz)) {
                    int xa = min(OUTD - 1, max(0, (int)floorf((lx + hdx) / vx)));
                    int ya = min(OUTD - 1, max(0, (int)floorf((ly + hdy) / vy)));
                    int za = min(OUTD - 1, max(0, (int)floorf(sz / vz)));
                    hit = (xa == xi) && (ya == yi) && (za == zi);
                }
            }
            unsigned mask = __ballot_sync(0xffffffffu, hit);
            while (mask) {
                int src = __ffs(mask) - 1;
                mask &= mask - 1;
                int pid = base + src;
                float2 v = ((const float2*)(feat + (size_t)pid * NCH))[lane];
                mx0 = fmaxf(mx0, v.x);
                mx1 = fmaxf(mx1, v.y);
            }
        }
    }
    o[lane] = make_float2(mx0, mx1);
}

// ---------------------------------------------------------------------------
extern "C" void kernel_launch(void* const* d_in, const int* in_sizes, int n_in,
                              void* d_out, int out_size)
{
    const float* rois = (const float*)d_in[0];       // (128, 7)
    const float* pts  = (const float*)d_in[1];       // (160000, 3)
    const float* feat = (const float*)d_in[2];       // (160000, 64)
    float* out = (float*)d_out;                      // (128, 12, 12, 12, 64)

    zero_counts_kernel<<<(NRV + 255) / 256, 256>>>();
    build_lists_kernel<<<(N_PTS + 255) / 256, 256>>>(rois, pts);
    pool_kernel<<<NRV / 8, 256>>>(rois, pts, feat, out);  // 8 warps/block, 1 warp/voxel
}